// round 1
// baseline (speedup 1.0000x reference)
#include <cuda_runtime.h>
#include <cuda_bf16.h>

#define NN 50000
#define NE 800000
#define NG 128
#define DD 128
#define HH 512
#define H2 1024
#define NL 4
#define BN_SCALE 0.9999950000374997f

// Scratch (static device arrays; no allocation in kernel_launch)
__device__ float g_Z[NN * HH];      // aggregated features (self + neighbor sum); conv1 uses first NN*DD
__device__ float g_T[NN * H2];      // hidden activations after MLP layer 1
__device__ float g_Hb[NN * HH];     // node features h
__device__ float g_vf[NG * HH];     // virtual-node features
__device__ float g_pl[NG * HH];     // pooled + vfeat
__device__ float g_zv[NG * H2];     // virtual MLP hidden
__device__ float g_cnt[NG];         // node counts per graph

__global__ void k_copy4(const float4* __restrict__ a, float4* __restrict__ b, int n4) {
    int i = blockIdx.x * blockDim.x + threadIdx.x;
    if (i < n4) b[i] = a[i];
}

__global__ void k_zero(float* __restrict__ p, int n) {
    int i = blockIdx.x * blockDim.x + threadIdx.x;
    if (i < n) p[i] = 0.0f;
}

__global__ void k_vfinit(const float* __restrict__ vemb, float* __restrict__ vf) {
    int i = blockIdx.x * blockDim.x + threadIdx.x;
    if (i < NG * HH) vf[i] = vemb[i & (HH - 1)];
}

// h[n] += vfeat[batch[n]]; Z[n] = h[n]   (float4 over N*HH/4)
__global__ void k_addvn(float4* __restrict__ Hb, float4* __restrict__ Z,
                        const float4* __restrict__ vf, const int* __restrict__ batch) {
    int i = blockIdx.x * blockDim.x + threadIdx.x;
    if (i >= NN * (HH / 4)) return;
    int n = i >> 7, c = i & 127;
    int g = batch[n];
    float4 h = Hb[i];
    float4 v = vf[(g << 7) + c];
    h.x += v.x; h.y += v.y; h.z += v.z; h.w += v.w;
    Hb[i] = h;
    Z[i] = h;
}

// Z[dst[e]] += h[src[e]]  (float4 vector atomics, sm_90+)
__global__ void k_scatter(const float4* __restrict__ h, float4* __restrict__ Z,
                          const int* __restrict__ src, const int* __restrict__ dst,
                          int shift, int mask, int total) {
    int i = blockIdx.x * blockDim.x + threadIdx.x;
    if (i >= total) return;
    int e = i >> shift, c = i & mask;
    float4 v = h[(src[e] << shift) + c];
    atomicAdd(&Z[(dst[e] << shift) + c], v);
}

// acc[batch[n]] += h[n]  (float4 vector atomics; HH fixed)
__global__ void k_segsum(const float4* __restrict__ h, float4* __restrict__ acc,
                         const int* __restrict__ batch) {
    int i = blockIdx.x * blockDim.x + threadIdx.x;
    if (i >= NN * (HH / 4)) return;
    int n = i >> 7, c = i & 127;
    atomicAdd(&acc[(batch[n] << 7) + c], h[i]);
}

__global__ void k_count(float* __restrict__ cnt, const int* __restrict__ batch) {
    int i = blockIdx.x * blockDim.x + threadIdx.x;
    if (i < NN) atomicAdd(&cnt[batch[i]], 1.0f);
}

__global__ void k_div(float* __restrict__ out, const float* __restrict__ cnt) {
    int i = blockIdx.x * blockDim.x + threadIdx.x;
    if (i < NG * HH) out[i] /= fmaxf(cnt[i >> 9], 1.0f);
}

// C[M,Nc] = epilogue(A[M,K] @ B[K,Nc])
// epilogue: v = (acc + bias[c]) * (gamma[c]*BN_SCALE) + beta[c]; optional ReLU
// Tiles: BM=BN=64, BK=16, 256 threads, 4x4 micro-tile per thread.
// Requires Nc % 64 == 0, K % 16 == 0 (true for all call sites: Nc in {512,1024}, K in {128,512,1024}).
__global__ void __launch_bounds__(256)
k_gemm(const float* __restrict__ A, const float* __restrict__ B,
       const float* __restrict__ bias, const float* __restrict__ gamma,
       const float* __restrict__ beta, float* __restrict__ C,
       int M, int Nc, int K, int relu) {
    __shared__ float As[16][65];   // [k][m], padded
    __shared__ float Bs[16][64];   // [k][n]

    int tid = threadIdx.x;
    int tx = tid & 15;
    int ty = tid >> 4;
    int rowBase = blockIdx.y * 64;
    int colBase = blockIdx.x * 64;

    // A-load mapping: row = tid/4 (0..63), kchunk = (tid%4)*4
    int ar = tid >> 2;
    int ak = (tid & 3) << 2;
    int aRow = rowBase + ar;
    bool aValid = (aRow < M);
    // B-load mapping: krow = tid/16 (0..15), ncol = (tid%16)*4
    int bk = ty;
    int bn = tx << 2;

    float acc[4][4];
    #pragma unroll
    for (int i = 0; i < 4; i++)
        #pragma unroll
        for (int j = 0; j < 4; j++) acc[i][j] = 0.0f;

    for (int k0 = 0; k0 < K; k0 += 16) {
        float4 av = make_float4(0.f, 0.f, 0.f, 0.f);
        if (aValid) av = *(const float4*)&A[aRow * K + k0 + ak];
        As[ak + 0][ar] = av.x;
        As[ak + 1][ar] = av.y;
        As[ak + 2][ar] = av.z;
        As[ak + 3][ar] = av.w;
        *(float4*)&Bs[bk][bn] = *(const float4*)&B[(k0 + bk) * Nc + colBase + bn];
        __syncthreads();

        #pragma unroll
        for (int k = 0; k < 16; k++) {
            float a0 = As[k][ty * 4 + 0];
            float a1 = As[k][ty * 4 + 1];
            float a2 = As[k][ty * 4 + 2];
            float a3 = As[k][ty * 4 + 3];
            float4 bv = *(const float4*)&Bs[k][tx * 4];
            acc[0][0] += a0 * bv.x; acc[0][1] += a0 * bv.y; acc[0][2] += a0 * bv.z; acc[0][3] += a0 * bv.w;
            acc[1][0] += a1 * bv.x; acc[1][1] += a1 * bv.y; acc[1][2] += a1 * bv.z; acc[1][3] += a1 * bv.w;
            acc[2][0] += a2 * bv.x; acc[2][1] += a2 * bv.y; acc[2][2] += a2 * bv.z; acc[2][3] += a2 * bv.w;
            acc[3][0] += a3 * bv.x; acc[3][1] += a3 * bv.y; acc[3][2] += a3 * bv.z; acc[3][3] += a3 * bv.w;
        }
        __syncthreads();
    }

    #pragma unroll
    for (int i = 0; i < 4; i++) {
        int r = rowBase + ty * 4 + i;
        if (r >= M) continue;
        #pragma unroll
        for (int j = 0; j < 4; j++) {
            int c = colBase + tx * 4 + j;
            float v = (acc[i][j] + bias[c]) * (gamma[c] * BN_SCALE) + beta[c];
            if (relu) v = fmaxf(v, 0.0f);
            C[r * Nc + c] = v;
        }
    }
}

extern "C" void kernel_launch(void* const* d_in, const int* in_sizes, int n_in,
                              void* d_out, int out_size) {
    const float* x      = (const float*)d_in[0];
    const int*   ei     = (const int*)d_in[1];
    const int*   batch  = (const int*)d_in[2];
    const float* c1_W1  = (const float*)d_in[3];
    const float* c1_b1  = (const float*)d_in[4];
    const float* c1_g1  = (const float*)d_in[5];
    const float* c1_be1 = (const float*)d_in[6];
    const float* c1_W2  = (const float*)d_in[7];
    const float* c1_b2  = (const float*)d_in[8];
    const float* bn1_g  = (const float*)d_in[9];
    const float* bn1_b  = (const float*)d_in[10];
    const float* cs_W1  = (const float*)d_in[11];
    const float* cs_b1  = (const float*)d_in[12];
    const float* cs_g1  = (const float*)d_in[13];
    const float* cs_be1 = (const float*)d_in[14];
    const float* cs_W2  = (const float*)d_in[15];
    const float* cs_b2  = (const float*)d_in[16];
    const float* bns_g  = (const float*)d_in[17];
    const float* bns_b  = (const float*)d_in[18];
    const float* vemb   = (const float*)d_in[19];
    const float* v_W1   = (const float*)d_in[20];
    const float* v_b1   = (const float*)d_in[21];
    const float* v_g1   = (const float*)d_in[22];
    const float* v_be1  = (const float*)d_in[23];
    const float* v_W2   = (const float*)d_in[24];
    const float* v_b2   = (const float*)d_in[25];
    const float* v_g2   = (const float*)d_in[26];
    const float* v_be2  = (const float*)d_in[27];
    float* out = (float*)d_out;

    const int* srcI = ei;
    const int* dstI = ei + NE;

    float *Z, *T, *Hb, *VF, *PL, *ZV, *CNT;
    cudaGetSymbolAddress((void**)&Z,   g_Z);
    cudaGetSymbolAddress((void**)&T,   g_T);
    cudaGetSymbolAddress((void**)&Hb,  g_Hb);
    cudaGetSymbolAddress((void**)&VF,  g_vf);
    cudaGetSymbolAddress((void**)&PL,  g_pl);
    cudaGetSymbolAddress((void**)&ZV,  g_zv);
    cudaGetSymbolAddress((void**)&CNT, g_cnt);

    const int TB = 256;

    // virtual node init: vfeat[g] = vemb[0]
    k_vfinit<<<(NG * HH + TB - 1) / TB, TB>>>(vemb, VF);

    // ---- conv1: F=128 -> 1024 -> 512 ----
    k_copy4<<<(NN * DD / 4 + TB - 1) / TB, TB>>>((const float4*)x, (float4*)Z, NN * DD / 4);
    {
        int total = NE * (DD / 4);
        k_scatter<<<(total + TB - 1) / TB, TB>>>((const float4*)x, (float4*)Z, srcI, dstI, 5, 31, total);
    }
    dim3 g1(H2 / 64, (NN + 63) / 64);
    dim3 g2(HH / 64, (NN + 63) / 64);
    k_gemm<<<g1, 256>>>(Z, c1_W1, c1_b1, c1_g1, c1_be1, T, NN, H2, DD, 1);
    k_gemm<<<g2, 256>>>(T, c1_W2, c1_b2, bn1_g, bn1_b, Hb, NN, HH, H2, 1);

    // ---- L extra GIN layers with virtual node ----
    for (int i = 0; i < NL; i++) {
        k_addvn<<<(NN * (HH / 4) + TB - 1) / TB, TB>>>((float4*)Hb, (float4*)Z, (const float4*)VF, batch);
        {
            int total = NE * (HH / 4);
            k_scatter<<<(total + TB - 1) / TB, TB>>>((const float4*)Hb, (float4*)Z, srcI, dstI, 7, 127, total);
        }
        k_gemm<<<g1, 256>>>(Z, cs_W1 + (size_t)i * HH * H2, cs_b1 + i * H2, cs_g1 + i * H2,
                            cs_be1 + i * H2, T, NN, H2, HH, 1);
        k_gemm<<<g2, 256>>>(T, cs_W2 + (size_t)i * H2 * HH, cs_b2 + i * HH, bns_g + i * HH,
                            bns_b + i * HH, Hb, NN, HH, H2, (i < NL - 1) ? 1 : 0);

        if (i < NL - 1) {
            // pooled = vfeat + segment_sum(h, batch)
            k_copy4<<<(NG * HH / 4 + TB - 1) / TB, TB>>>((const float4*)VF, (float4*)PL, NG * HH / 4);
            k_segsum<<<(NN * (HH / 4) + TB - 1) / TB, TB>>>((const float4*)Hb, (float4*)PL, batch);
            dim3 gv1(H2 / 64, (NG + 63) / 64);
            dim3 gv2(HH / 64, (NG + 63) / 64);
            k_gemm<<<gv1, 256>>>(PL, v_W1, v_b1, v_g1, v_be1, ZV, NG, H2, HH, 1);
            k_gemm<<<gv2, 256>>>(ZV, v_W2, v_b2, v_g2, v_be2, VF, NG, HH, H2, 1);
        }
    }

    // ---- readout: mean pool per graph ----
    k_zero<<<(NG * HH + TB - 1) / TB, TB>>>(out, NG * HH);
    k_zero<<<1, NG>>>(CNT, NG);
    k_segsum<<<(NN * (HH / 4) + TB - 1) / TB, TB>>>((const float4*)Hb, (float4*)out, batch);
    k_count<<<(NN + TB - 1) / TB, TB>>>(CNT, batch);
    k_div<<<(NG * HH + TB - 1) / TB, TB>>>(out, CNT);
}

// round 3
// speedup vs baseline: 2.4533x; 2.4533x over previous
#include <cuda_runtime.h>
#include <cuda_bf16.h>
#include <cstdint>

#define NN 50000
#define NE 800000
#define NG 128
#define DD 128
#define HH 512
#define H2 1024
#define NL 4
#define BN_SCALE 0.9999950000374997f

// ---------------- scratch (static device arrays) ----------------
__device__ float g_Z[NN * HH];                 // scatter target (fp32)
__device__ float g_Hb[NN * HH];                // node features h (fp32)
__device__ __nv_bfloat16 g_Ahi[NN * HH];       // split of Z (GEMM-1 input)
__device__ __nv_bfloat16 g_Alo[NN * HH];
__device__ __nv_bfloat16 g_Thi[NN * H2];       // hidden activations (GEMM-1 out / GEMM-2 in)
__device__ __nv_bfloat16 g_Tlo[NN * H2];
__device__ float g_vf[NG * HH];
__device__ float g_pl[NG * HH];
__device__ __nv_bfloat16 g_plhi[NG * HH];
__device__ __nv_bfloat16 g_pllo[NG * HH];
__device__ __nv_bfloat16 g_zvhi[NG * H2];
__device__ __nv_bfloat16 g_zvlo[NG * H2];
__device__ float g_cnt[NG];

// transposed + hi/lo-split weights: [N,K] bf16
#define WTOT 5898240
__device__ __nv_bfloat16 g_Whi[WTOT];
__device__ __nv_bfloat16 g_Wlo[WTOT];

// ---------------- helpers ----------------
__device__ __forceinline__ uint32_t smem_u32(const void* p) {
    uint32_t a;
    asm("{ .reg .u64 t; cvta.to.shared.u64 t, %1; cvt.u32.u64 %0, t; }" : "=r"(a) : "l"(p));
    return a;
}
#define SWZ(b) ((b) ^ (((b) >> 3) & 0x70))

__device__ __forceinline__ void cp_async16(uint32_t dst, const void* src, unsigned sz) {
    asm volatile("cp.async.cg.shared.global [%0], [%1], 16, %2;" :: "r"(dst), "l"(src), "r"(sz));
}
__device__ __forceinline__ void ldmx4(uint32_t* r, uint32_t addr) {
    asm volatile("ldmatrix.sync.aligned.m8n8.x4.shared.b16 {%0,%1,%2,%3}, [%4];"
                 : "=r"(r[0]), "=r"(r[1]), "=r"(r[2]), "=r"(r[3]) : "r"(addr));
}
__device__ __forceinline__ void mma_bf16(float* d, const uint32_t* a, uint32_t b0, uint32_t b1) {
    asm volatile("mma.sync.aligned.m16n8k16.row.col.f32.bf16.bf16.f32 "
                 "{%0,%1,%2,%3}, {%4,%5,%6,%7}, {%8,%9}, {%0,%1,%2,%3};"
                 : "+f"(d[0]), "+f"(d[1]), "+f"(d[2]), "+f"(d[3])
                 : "r"(a[0]), "r"(a[1]), "r"(a[2]), "r"(a[3]), "r"(b0), "r"(b1));
}

// ---------------- GEMM: C[M,N] = epi( (Ahi+Alo)[M,K] @ (Bhi+Blo)[N,K]^T ) ----------------
// BM=128, BN=128, K-chunk=64, 256 threads (8 warps of 32x64), cp.async double buffer.
// mode 0: write fp32 C.  mode 1: write bf16 hi/lo pair (Ohi/Olo).
#define SMBUF 65536
#define SM_AHI 0
#define SM_ALO 16384
#define SM_BHI 32768
#define SM_BLO 49152

__global__ void __launch_bounds__(256, 1)
k_gemm_mma(const __nv_bfloat16* __restrict__ Ahi, const __nv_bfloat16* __restrict__ Alo,
           const __nv_bfloat16* __restrict__ Bhi, const __nv_bfloat16* __restrict__ Blo,
           const float* __restrict__ bias, const float* __restrict__ gamma,
           const float* __restrict__ beta,
           float* __restrict__ C, __nv_bfloat16* __restrict__ Ohi, __nv_bfloat16* __restrict__ Olo,
           int M, int N, int K, int relu, int mode) {
    extern __shared__ char smem[];
    uint32_t sb = smem_u32(smem);
    int tid = threadIdx.x;
    int lane = tid & 31, wid = tid >> 5;
    int wm = (wid & 3) * 32;      // warp row offset in tile
    int wn = (wid >> 2) * 64;     // warp col offset in tile
    int rowBase = blockIdx.y * 128;
    int colBase = blockIdx.x * 128;

    float acc[2][8][4];
    #pragma unroll
    for (int i = 0; i < 2; i++)
        #pragma unroll
        for (int j = 0; j < 8; j++)
            #pragma unroll
            for (int k = 0; k < 4; k++) acc[i][j][k] = 0.0f;

    // ---- chunk loader: 4 tiles of [128 x 64] bf16 (16KB each) ----
    auto load_chunk = [&](int buf, int k0) {
        uint32_t base = sb + buf * SMBUF;
        #pragma unroll
        for (int it = 0; it < 4; it++) {
            int idx = tid + it * 256;
            int row = idx >> 3;
            int ch = (idx & 7) * 16;          // byte offset within 128B row
            uint32_t soff = SWZ((uint32_t)(row * 128 + ch));
            int gr = rowBase + row;
            unsigned sz = (gr < M) ? 16u : 0u;
            int grc = (gr < M) ? gr : 0;
            const char* pAhi = (const char*)(Ahi + (size_t)grc * K + k0) + ch;
            const char* pAlo = (const char*)(Alo + (size_t)grc * K + k0) + ch;
            cp_async16(base + SM_AHI + soff, pAhi, sz);
            cp_async16(base + SM_ALO + soff, pAlo, sz);
            int gc = colBase + row;           // N is always a multiple of 128
            const char* pBhi = (const char*)(Bhi + (size_t)gc * K + k0) + ch;
            const char* pBlo = (const char*)(Blo + (size_t)gc * K + k0) + ch;
            cp_async16(base + SM_BHI + soff, pBhi, 16u);
            cp_async16(base + SM_BLO + soff, pBlo, 16u);
        }
    };

    auto compute_chunk = [&](int buf) {
        uint32_t aHiB = sb + buf * SMBUF + SM_AHI;
        uint32_t aLoB = sb + buf * SMBUF + SM_ALO;
        uint32_t bHiB = sb + buf * SMBUF + SM_BHI;
        uint32_t bLoB = sb + buf * SMBUF + SM_BLO;
        int mat = lane >> 3, l7 = lane & 7;
        #pragma unroll
        for (int ks = 0; ks < 4; ks++) {
            uint32_t ahi[2][4], alo[2][4];
            #pragma unroll
            for (int mt = 0; mt < 2; mt++) {
                int row = wm + mt * 16 + ((mat & 1) << 3) + l7;
                int byt = ks * 32 + ((mat >> 1) << 4);
                uint32_t off = SWZ((uint32_t)(row * 128 + byt));
                ldmx4(ahi[mt], aHiB + off);
                ldmx4(alo[mt], aLoB + off);
            }
            #pragma unroll
            for (int np = 0; np < 4; np++) {
                int row = wn + np * 16 + ((mat >> 1) << 3) + l7;
                int byt = ks * 32 + ((mat & 1) << 4);
                uint32_t off = SWZ((uint32_t)(row * 128 + byt));
                uint32_t bhi[4], blo[4];
                ldmx4(bhi, bHiB + off);
                ldmx4(blo, bLoB + off);
                // interleave the 3 passes across 4 accumulators to break RAW chains
                #pragma unroll
                for (int mt = 0; mt < 2; mt++)
                    #pragma unroll
                    for (int h = 0; h < 2; h++)
                        mma_bf16(acc[mt][np * 2 + h], ahi[mt], bhi[2 * h], bhi[2 * h + 1]);
                #pragma unroll
                for (int mt = 0; mt < 2; mt++)
                    #pragma unroll
                    for (int h = 0; h < 2; h++)
                        mma_bf16(acc[mt][np * 2 + h], ahi[mt], blo[2 * h], blo[2 * h + 1]);
                #pragma unroll
                for (int mt = 0; mt < 2; mt++)
                    #pragma unroll
                    for (int h = 0; h < 2; h++)
                        mma_bf16(acc[mt][np * 2 + h], alo[mt], bhi[2 * h], bhi[2 * h + 1]);
            }
        }
    };

    int nk = K >> 6;
    load_chunk(0, 0);
    asm volatile("cp.async.commit_group;" ::: "memory");
    for (int c = 0; c < nk; c++) {
        if (c + 1 < nk) {
            load_chunk((c + 1) & 1, (c + 1) * 64);
            asm volatile("cp.async.commit_group;" ::: "memory");
            asm volatile("cp.async.wait_group 1;" ::: "memory");
        } else {
            asm volatile("cp.async.wait_group 0;" ::: "memory");
        }
        __syncthreads();
        compute_chunk(c & 1);
        __syncthreads();
    }

    // ---- epilogue ----
    int lm = lane >> 2;
    int ln = (lane & 3) * 2;
    #pragma unroll
    for (int mt = 0; mt < 2; mt++) {
        #pragma unroll
        for (int hr = 0; hr < 2; hr++) {
            int m = rowBase + wm + mt * 16 + hr * 8 + lm;
            if (m >= M) continue;
            #pragma unroll
            for (int nt = 0; nt < 8; nt++) {
                int n = colBase + wn + nt * 8 + ln;
                float v0 = acc[mt][nt][hr * 2 + 0];
                float v1 = acc[mt][nt][hr * 2 + 1];
                v0 = (v0 + __ldg(bias + n)) * (__ldg(gamma + n) * BN_SCALE) + __ldg(beta + n);
                v1 = (v1 + __ldg(bias + n + 1)) * (__ldg(gamma + n + 1) * BN_SCALE) + __ldg(beta + n + 1);
                if (relu) { v0 = fmaxf(v0, 0.f); v1 = fmaxf(v1, 0.f); }
                if (mode == 0) {
                    float2 o; o.x = v0; o.y = v1;
                    *(float2*)(C + (size_t)m * N + n) = o;
                } else {
                    uint32_t u0 = __float_as_uint(v0), u1 = __float_as_uint(v1);
                    uint32_t hv = __byte_perm(u0, u1, 0x7632);
                    float l0 = v0 - __uint_as_float(u0 & 0xFFFF0000u);
                    float l1 = v1 - __uint_as_float(u1 & 0xFFFF0000u);
                    uint32_t lv;
                    asm("cvt.rn.bf16x2.f32 %0, %1, %2;" : "=r"(lv) : "f"(l1), "f"(l0));
                    *(uint32_t*)(Ohi + (size_t)m * N + n) = hv;
                    *(uint32_t*)(Olo + (size_t)m * N + n) = lv;
                }
            }
        }
    }
}

// ---------------- weight prep: transpose + hi/lo split ----------------
__global__ void k_wprep(const float* __restrict__ W, __nv_bfloat16* __restrict__ hi,
                        __nv_bfloat16* __restrict__ lo, int K, int N) {
    int i = blockIdx.x * blockDim.x + threadIdx.x;
    if (i >= N * K) return;
    int n = i / K, k = i - n * K;
    float v = W[(size_t)k * N + n];
    uint32_t u = __float_as_uint(v);
    hi[i] = __ushort_as_bfloat16((unsigned short)(u >> 16));
    lo[i] = __float2bfloat16(v - __uint_as_float(u & 0xFFFF0000u));
}

// ---------------- fp32 -> bf16 hi/lo split (activations) ----------------
__global__ void k_conv(const float4* __restrict__ in, uint32_t* __restrict__ hi,
                       uint32_t* __restrict__ lo, int n4) {
    int i = blockIdx.x * blockDim.x + threadIdx.x;
    if (i >= n4) return;
    float4 v = in[i];
    uint32_t ux = __float_as_uint(v.x), uy = __float_as_uint(v.y);
    uint32_t uz = __float_as_uint(v.z), uw = __float_as_uint(v.w);
    uint32_t h0 = __byte_perm(ux, uy, 0x7632);
    uint32_t h1 = __byte_perm(uz, uw, 0x7632);
    float lx = v.x - __uint_as_float(ux & 0xFFFF0000u);
    float ly = v.y - __uint_as_float(uy & 0xFFFF0000u);
    float lz = v.z - __uint_as_float(uz & 0xFFFF0000u);
    float lw = v.w - __uint_as_float(uw & 0xFFFF0000u);
    uint32_t l0, l1;
    asm("cvt.rn.bf16x2.f32 %0, %1, %2;" : "=r"(l0) : "f"(ly), "f"(lx));
    asm("cvt.rn.bf16x2.f32 %0, %1, %2;" : "=r"(l1) : "f"(lw), "f"(lz));
    hi[2 * i] = h0; hi[2 * i + 1] = h1;
    lo[2 * i] = l0; lo[2 * i + 1] = l1;
}

// ---------------- graph/pool kernels ----------------
__global__ void k_copy4(const float4* __restrict__ a, float4* __restrict__ b, int n4) {
    int i = blockIdx.x * blockDim.x + threadIdx.x;
    if (i < n4) b[i] = a[i];
}
__global__ void k_zero(float* __restrict__ p, int n) {
    int i = blockIdx.x * blockDim.x + threadIdx.x;
    if (i < n) p[i] = 0.0f;
}
__global__ void k_vfinit(const float* __restrict__ vemb, float* __restrict__ vf) {
    int i = blockIdx.x * blockDim.x + threadIdx.x;
    if (i < NG * HH) vf[i] = vemb[i & (HH - 1)];
}
__global__ void k_addvn(float4* __restrict__ Hb, float4* __restrict__ Z,
                        const float4* __restrict__ vf, const int* __restrict__ batch) {
    int i = blockIdx.x * blockDim.x + threadIdx.x;
    if (i >= NN * (HH / 4)) return;
    int n = i >> 7, c = i & 127;
    int g = batch[n];
    float4 h = Hb[i];
    float4 v = vf[(g << 7) + c];
    h.x += v.x; h.y += v.y; h.z += v.z; h.w += v.w;
    Hb[i] = h;
    Z[i] = h;
}
__global__ void k_scatter(const float4* __restrict__ h, float4* __restrict__ Z,
                          const int* __restrict__ src, const int* __restrict__ dst,
                          int shift, int mask, int total) {
    int i = blockIdx.x * blockDim.x + threadIdx.x;
    if (i >= total) return;
    int e = i >> shift, c = i & mask;
    float4 v = h[(src[e] << shift) + c];
    atomicAdd(&Z[(dst[e] << shift) + c], v);
}
__global__ void k_segsum(const float4* __restrict__ h, float4* __restrict__ acc,
                         const int* __restrict__ batch) {
    int i = blockIdx.x * blockDim.x + threadIdx.x;
    if (i >= NN * (HH / 4)) return;
    int n = i >> 7, c = i & 127;
    atomicAdd(&acc[(batch[n] << 7) + c], h[i]);
}
__global__ void k_count(float* __restrict__ cnt, const int* __restrict__ batch) {
    int i = blockIdx.x * blockDim.x + threadIdx.x;
    if (i < NN) atomicAdd(&cnt[batch[i]], 1.0f);
}
__global__ void k_div(float* __restrict__ out, const float* __restrict__ cnt) {
    int i = blockIdx.x * blockDim.x + threadIdx.x;
    if (i < NG * HH) out[i] /= fmaxf(cnt[i >> 9], 1.0f);
}

// weight offsets (elements) into g_Whi/g_Wlo
#define OFF_C1W1 0
#define OFF_C1W2 131072
#define OFF_CSW1 655360
#define OFF_CSW2 2752512
#define OFF_VW1  4849664
#define OFF_VW2  5373952

extern "C" void kernel_launch(void* const* d_in, const int* in_sizes, int n_in,
                              void* d_out, int out_size) {
    const float* x      = (const float*)d_in[0];
    const int*   ei     = (const int*)d_in[1];
    const int*   batch  = (const int*)d_in[2];
    const float* c1_W1  = (const float*)d_in[3];
    const float* c1_b1  = (const float*)d_in[4];
    const float* c1_g1  = (const float*)d_in[5];
    const float* c1_be1 = (const float*)d_in[6];
    const float* c1_W2  = (const float*)d_in[7];
    const float* c1_b2  = (const float*)d_in[8];
    const float* bn1_g  = (const float*)d_in[9];
    const float* bn1_b  = (const float*)d_in[10];
    const float* cs_W1  = (const float*)d_in[11];
    const float* cs_b1  = (const float*)d_in[12];
    const float* cs_g1  = (const float*)d_in[13];
    const float* cs_be1 = (const float*)d_in[14];
    const float* cs_W2  = (const float*)d_in[15];
    const float* cs_b2  = (const float*)d_in[16];
    const float* bns_g  = (const float*)d_in[17];
    const float* bns_b  = (const float*)d_in[18];
    const float* vemb   = (const float*)d_in[19];
    const float* v_W1   = (const float*)d_in[20];
    const float* v_b1   = (const float*)d_in[21];
    const float* v_g1   = (const float*)d_in[22];
    const float* v_be1  = (const float*)d_in[23];
    const float* v_W2   = (const float*)d_in[24];
    const float* v_b2   = (const float*)d_in[25];
    const float* v_g2   = (const float*)d_in[26];
    const float* v_be2  = (const float*)d_in[27];
    float* out = (float*)d_out;

    const int* srcI = ei;
    const int* dstI = ei + NE;

    float *Z, *Hb, *VF, *PL, *CNT;
    __nv_bfloat16 *Whi, *Wlo, *Ahi, *Alo, *Thi, *Tlo, *PLhi, *PLlo, *ZVhi, *ZVlo;
    cudaGetSymbolAddress((void**)&Z,    g_Z);
    cudaGetSymbolAddress((void**)&Hb,   g_Hb);
    cudaGetSymbolAddress((void**)&VF,   g_vf);
    cudaGetSymbolAddress((void**)&PL,   g_pl);
    cudaGetSymbolAddress((void**)&CNT,  g_cnt);
    cudaGetSymbolAddress((void**)&Whi,  g_Whi);
    cudaGetSymbolAddress((void**)&Wlo,  g_Wlo);
    cudaGetSymbolAddress((void**)&Ahi,  g_Ahi);
    cudaGetSymbolAddress((void**)&Alo,  g_Alo);
    cudaGetSymbolAddress((void**)&Thi,  g_Thi);
    cudaGetSymbolAddress((void**)&Tlo,  g_Tlo);
    cudaGetSymbolAddress((void**)&PLhi, g_plhi);
    cudaGetSymbolAddress((void**)&PLlo, g_pllo);
    cudaGetSymbolAddress((void**)&ZVhi, g_zvhi);
    cudaGetSymbolAddress((void**)&ZVlo, g_zvlo);

    cudaFuncSetAttribute(k_gemm_mma, cudaFuncAttributeMaxDynamicSharedMemorySize, 2 * SMBUF);

    const int TB = 256;
    auto blks = [](int n) { return (n + 255) / 256; };

    // ---- weight prep (transpose + split) ----
    k_wprep<<<blks(H2 * DD), TB>>>(c1_W1, Whi + OFF_C1W1, Wlo + OFF_C1W1, DD, H2);
    k_wprep<<<blks(HH * H2), TB>>>(c1_W2, Whi + OFF_C1W2, Wlo + OFF_C1W2, H2, HH);
    for (int i = 0; i < NL; i++) {
        k_wprep<<<blks(H2 * HH), TB>>>(cs_W1 + (size_t)i * HH * H2,
                                       Whi + OFF_CSW1 + (size_t)i * H2 * HH,
                                       Wlo + OFF_CSW1 + (size_t)i * H2 * HH, HH, H2);
        k_wprep<<<blks(HH * H2), TB>>>(cs_W2 + (size_t)i * H2 * HH,
                                       Whi + OFF_CSW2 + (size_t)i * H2 * HH,
                                       Wlo + OFF_CSW2 + (size_t)i * H2 * HH, H2, HH);
    }
    k_wprep<<<blks(H2 * HH), TB>>>(v_W1, Whi + OFF_VW1, Wlo + OFF_VW1, HH, H2);
    k_wprep<<<blks(HH * H2), TB>>>(v_W2, Whi + OFF_VW2, Wlo + OFF_VW2, H2, HH);

    k_vfinit<<<blks(NG * HH), TB>>>(vemb, VF);

    dim3 gN1(H2 / 128, (NN + 127) / 128);   // N=1024
    dim3 gN2(HH / 128, (NN + 127) / 128);   // N=512
    dim3 gv1(H2 / 128, 1);
    dim3 gv2(HH / 128, 1);

    // ---- conv1: 128 -> 1024 -> 512 ----
    k_copy4<<<blks(NN * DD / 4), TB>>>((const float4*)x, (float4*)Z, NN * DD / 4);
    {
        int total = NE * (DD / 4);
        k_scatter<<<blks(total), TB>>>((const float4*)x, (float4*)Z, srcI, dstI, 5, 31, total);
    }
    k_conv<<<blks(NN * DD / 4), TB>>>((const float4*)Z, (uint32_t*)Ahi, (uint32_t*)Alo, NN * DD / 4);
    k_gemm_mma<<<gN1, 256, 2 * SMBUF>>>(Ahi, Alo, Whi + OFF_C1W1, Wlo + OFF_C1W1,
                                        c1_b1, c1_g1, c1_be1, nullptr, Thi, Tlo,
                                        NN, H2, DD, 1, 1);
    k_gemm_mma<<<gN2, 256, 2 * SMBUF>>>(Thi, Tlo, Whi + OFF_C1W2, Wlo + OFF_C1W2,
                                        c1_b2, bn1_g, bn1_b, Hb, nullptr, nullptr,
                                        NN, HH, H2, 1, 0);

    // ---- L GIN layers with virtual node ----
    for (int i = 0; i < NL; i++) {
        k_addvn<<<blks(NN * (HH / 4)), TB>>>((float4*)Hb, (float4*)Z, (const float4*)VF, batch);
        {
            int total = NE * (HH / 4);
            k_scatter<<<blks(total), TB>>>((const float4*)Hb, (float4*)Z, srcI, dstI, 7, 127, total);
        }
        k_conv<<<blks(NN * HH / 4), TB>>>((const float4*)Z, (uint32_t*)Ahi, (uint32_t*)Alo, NN * HH / 4);
        k_gemm_mma<<<gN1, 256, 2 * SMBUF>>>(Ahi, Alo,
                                            Whi + OFF_CSW1 + (size_t)i * H2 * HH,
                                            Wlo + OFF_CSW1 + (size_t)i * H2 * HH,
                                            cs_b1 + i * H2, cs_g1 + i * H2, cs_be1 + i * H2,
                                            nullptr, Thi, Tlo, NN, H2, HH, 1, 1);
        k_gemm_mma<<<gN2, 256, 2 * SMBUF>>>(Thi, Tlo,
                                            Whi + OFF_CSW2 + (size_t)i * H2 * HH,
                                            Wlo + OFF_CSW2 + (size_t)i * H2 * HH,
                                            cs_b2 + i * HH, bns_g + i * HH, bns_b + i * HH,
                                            Hb, nullptr, nullptr, NN, HH, H2,
                                            (i < NL - 1) ? 1 : 0, 0);
        if (i < NL - 1) {
            k_copy4<<<blks(NG * HH / 4), TB>>>((const float4*)VF, (float4*)PL, NG * HH / 4);
            k_segsum<<<blks(NN * (HH / 4)), TB>>>((const float4*)Hb, (float4*)PL, batch);
            k_conv<<<blks(NG * HH / 4), TB>>>((const float4*)PL, (uint32_t*)PLhi, (uint32_t*)PLlo, NG * HH / 4);
            k_gemm_mma<<<gv1, 256, 2 * SMBUF>>>(PLhi, PLlo, Whi + OFF_VW1, Wlo + OFF_VW1,
                                                v_b1, v_g1, v_be1, nullptr, ZVhi, ZVlo,
                                                NG, H2, HH, 1, 1);
            k_gemm_mma<<<gv2, 256, 2 * SMBUF>>>(ZVhi, ZVlo, Whi + OFF_VW2, Wlo + OFF_VW2,
                                                v_b2, v_g2, v_be2, VF, nullptr, nullptr,
                                                NG, HH, H2, 1, 0);
        }
    }

    // ---- readout: mean pool ----
    k_zero<<<blks(NG * HH), TB>>>(out, NG * HH);
    k_zero<<<1, NG>>>(CNT, NG);
    k_segsum<<<blks(NN * (HH / 4)), TB>>>((const float4*)Hb, (float4*)out, batch);
    k_count<<<blks(NN), TB>>>(CNT, batch);
    k_div<<<blks(NG * HH), TB>>>(out, CNT);
}